// round 15
// baseline (speedup 1.0000x reference)
#include <cuda_runtime.h>
#include <cuda_fp16.h>
#include <cstdint>

#define BB 64
#define TSTEPS 512
#define HH 512

// ---------------- static device scratch ----------------
__device__ __align__(16) __half g_xh[TSTEPS * BB * 256];        // x fp16, [T][B][256]
__device__ __align__(16) __half g_h0[(TSTEPS + 1) * BB * HH];   // layer0 h seq, slot0 = 0
__device__ __align__(16) __half g_h1[(TSTEPS + 1) * BB * HH];   // layer1 h seq, slot0 = 0
__device__ unsigned g_c0;                                       // monotonic arrival counters
__device__ unsigned g_c1;

// ---------------- PTX helpers ----------------
__device__ __forceinline__ void ldsm4(uint32_t& r0, uint32_t& r1, uint32_t& r2, uint32_t& r3,
                                      uint32_t a) {
    asm volatile("ldmatrix.sync.aligned.m8n8.x4.shared.b16 {%0,%1,%2,%3}, [%4];\n"
                 : "=r"(r0), "=r"(r1), "=r"(r2), "=r"(r3) : "r"(a));
}
__device__ __forceinline__ void mma16816(float* c,
                                         uint32_t a0, uint32_t a1, uint32_t a2, uint32_t a3,
                                         uint32_t b0, uint32_t b1) {
    asm volatile("mma.sync.aligned.m16n8k16.row.col.f32.f16.f16.f32 "
                 "{%0,%1,%2,%3}, {%4,%5,%6,%7}, {%8,%9}, {%0,%1,%2,%3};\n"
                 : "+f"(c[0]), "+f"(c[1]), "+f"(c[2]), "+f"(c[3])
                 : "r"(a0), "r"(a1), "r"(a2), "r"(a3), "r"(b0), "r"(b1));
}
__device__ __forceinline__ unsigned ld_acq(const unsigned* p) {
    unsigned v;
    asm volatile("ld.acquire.gpu.global.u32 %0, [%1];" : "=r"(v) : "l"(p) : "memory");
    return v;
}
__device__ __forceinline__ void red_rel(unsigned* p) {
    asm volatile("red.release.gpu.global.add.u32 [%0], 1;" :: "l"(p) : "memory");
}
// warp-collective poll: all lanes spin on the same counter (one coalesced request)
__device__ __forceinline__ void wpoll(const unsigned* p, unsigned v) {
    while (ld_acq(p) < v) {}
}

// ---------------- A fragments direct from global (row-major, stride S halves) ----------------
// Warp covers rows [m0, m0+16) x k-halves [0, NJ*16) of A (caller pre-offsets k base).
// Fragment mapping identical to ldmatrix.x4 with rA=m0+(lane&15), akc=lane>>4.
template<int NJ>
__device__ __forceinline__ void load_afrag(uint32_t (&a)[NJ][4], const __half* A, int S,
                                           int m0, int lane) {
    int gid = lane >> 2, tig = lane & 3;
    const __half* p0 = A + (size_t)(m0 + gid) * S + tig * 2;
    const __half* p1 = p0 + 8 * S;
#pragma unroll
    for (int j = 0; j < NJ; j++) {
        a[j][0] = *(const uint32_t*)(p0 + j * 16);
        a[j][1] = *(const uint32_t*)(p1 + j * 16);
        a[j][2] = *(const uint32_t*)(p0 + j * 16 + 8);
        a[j][3] = *(const uint32_t*)(p1 + j * 16 + 8);
    }
}

// ---------------- GEMM on preloaded A fragments; B via ldsm from resident W ----------------
template<int NJ>
__device__ __forceinline__ void gemm_frag(float* acc, const uint32_t (&a)[NJ][4],
                                          uint32_t wsmb, int rowb, int wu0, int lane) {
    int bm = lane >> 3, bsw = lane & 7;
    uint32_t bb0 = wsmb + (lane & 7) * rowb;
#pragma unroll
    for (int p = 0; p < NJ / 2; p++) {
        int wu = wu0 + 4 * p;
#pragma unroll
        for (int nt = 0; nt < 4; nt++) {
            uint32_t b0, b1, b2, b3;
            ldsm4(b0, b1, b2, b3, bb0 + nt * 8 * rowb + (((wu + bm) ^ bsw) << 4));
            mma16816(acc + nt * 4, a[2*p][0],   a[2*p][1],   a[2*p][2],   a[2*p][3],   b0, b1);
            mma16816(acc + nt * 4, a[2*p+1][0], a[2*p+1][1], a[2*p+1][2], a[2*p+1][3], b2, b3);
        }
    }
}

// ---------------- init kernel: x convert + h slot0 zero + counters ----------------
__global__ void init_k(const float* __restrict__ x) {
    int i = blockIdx.x * 256 + threadIdx.x;
    int f2 = i & 127;
    int t  = (i >> 7) & 511;
    int b  = i >> 16;
    float2 v = *(const float2*)(x + ((b * 512 + t) * 256 + f2 * 2));
    *((__half2*)(g_xh + (t * 64 + b) * 256 + f2 * 2)) = __floats2half2_rn(v.x, v.y);
    if (i < 16384) {
        __half2 z = __floats2half2_rn(0.f, 0.f);
        ((__half2*)g_h0)[i] = z;
        ((__half2*)g_h1)[i] = z;
    }
    if (i == 0) { g_c0 = 0; g_c1 = 0; }
}

// ---------------- fused two-layer pipelined persistent kernel ----------------
// CTAs [0,64): layer 0.  CTAs [64,128): layer 1, one step behind.
// 512 threads = 16 warps = 4(m) x 4(k-quarter); each warp covers all 32 gate cols.
// A fragments loaded directly from global (no smem staging, no cp.async, 2 syncs/step).
template<int GRP>
__device__ __forceinline__ void run_group(char* dsm, int lx,
        const float* __restrict__ Wih, const float* __restrict__ Whh,
        const float* __restrict__ bih, const float* __restrict__ bhh,
        float* __restrict__ outp) {
    constexpr int KIN  = GRP ? 512 : 256;
    constexpr int KTOT = KIN + 512;
    constexpr int ROWB = KTOT * 2;                    // W smem row bytes
    constexpr int W_OFF = 1024;
    constexpr int ST_OFF = W_OFF + 32 * ROWB;         // dedicated stash region
    uint32_t smb = (uint32_t)__cvta_generic_to_shared(dsm);
    float* stash = (float*)(dsm + ST_OFF);            // 4 x [64 rows x 40 floats]
    float* bsm   = (float*)(dsm + 64);

    __half* hbuf  = GRP ? g_h1 : g_h0;
    unsigned* own = GRP ? &g_c1 : &g_c0;

    int tid = threadIdx.x, lane = tid & 31, w = tid >> 5;
    int m0 = (w & 3) * 16, kq = w >> 2;

    // ---- load & convert W slice: 32 rows ([Wih|Whh] along k), swizzled fp16, resident ----
    for (int idx = tid; idx < 32 * (KTOT / 4); idx += 512) {
        int n  = idx / (KTOT / 4);
        int kk = (idx % (KTOT / 4)) * 4;
        int gr = (n >> 3) * HH + lx * 8 + (n & 7);
        float4 v = (kk < KIN) ? *(const float4*)(Wih + (size_t)gr * KIN + kk)
                              : *(const float4*)(Whh + (size_t)gr * HH + (kk - KIN));
        __half2 p0 = __floats2half2_rn(v.x, v.y);
        __half2 p1 = __floats2half2_rn(v.z, v.w);
        char* dst = dsm + W_OFF + n * ROWB + (((kk >> 3) ^ (n & 7)) << 4) + (kk & 7) * 2;
        *(__half2*)dst       = p0;
        *(__half2*)(dst + 4) = p1;
    }
    if (tid < 32) {
        int gr = (tid >> 3) * HH + lx * 8 + (tid & 7);
        bsm[tid] = bih[gr] + bhh[gr];
    }
    __syncthreads();

    float cst = 0.f;                                  // c-state for (b=tid>>3, u=tid&7)
    float acc[16];
#pragma unroll
    for (int i = 0; i < 16; i++) acc[i] = 0.f;

    if (GRP == 0) {   // prologue: x contribution for step 1 (direct LDG fragments)
        uint32_t ax[4][4];
        load_afrag<4>(ax, g_xh + kq * 64, 256, m0, lane);
        gemm_frag<4>(acc, ax, smb + W_OFF, ROWB, kq * 8, lane);
    }

    for (int t = 1; t <= TSTEPS; t++) {
        if (GRP == 0) {
            // own recurrence: poll, load h fragments straight from global, gemm
            wpoll(&g_c0, 64u * (t - 1));
            uint32_t ah[8][4];
            load_afrag<8>(ah, g_h0 + (size_t)(t - 1) * BB * HH + kq * 128, 512, m0, lane);
            gemm_frag<8>(acc, ah, smb + W_OFF, ROWB, 32 + kq * 16, lane);
        } else {
            // h0[t] (usually already published) then own h1[t-1]
            wpoll(&g_c0, 64u * t);
            uint32_t ah0[8][4];
            load_afrag<8>(ah0, g_h0 + (size_t)t * BB * HH + kq * 128, 512, m0, lane);
            wpoll(&g_c1, 64u * (t - 1));
            uint32_t ah1[8][4];
            load_afrag<8>(ah1, g_h1 + (size_t)(t - 1) * BB * HH + kq * 128, 512, m0, lane);
            gemm_frag<8>(acc, ah0, smb + W_OFF, ROWB, kq * 16, lane);
            gemm_frag<8>(acc, ah1, smb + W_OFF, ROWB, 64 + kq * 16, lane);
        }

        // ---- stash partials (dedicated region, no pre-sync needed) ----
        {
            float* sp = stash + kq * 2560;
            int r0 = m0 + (lane >> 2), cb = 2 * (lane & 3);
#pragma unroll
            for (int nt = 0; nt < 4; nt++) {
                *(float2*)(sp + r0 * 40 + nt * 8 + cb)       =
                    make_float2(acc[nt * 4],     acc[nt * 4 + 1]);
                *(float2*)(sp + (r0 + 8) * 40 + nt * 8 + cb) =
                    make_float2(acc[nt * 4 + 2], acc[nt * 4 + 3]);
            }
        }
        __syncthreads();

        // ---- pointwise LSTM: thread owns (b = tid>>3, u = tid&7) ----
        {
            int b = tid >> 3, u = tid & 7;
            float zi = bsm[u], zf = bsm[8 + u], zg = bsm[16 + u], zo = bsm[24 + u];
#pragma unroll
            for (int q = 0; q < 4; q++) {
                const float* p = stash + q * 2560 + b * 40 + u;
                zi += p[0]; zf += p[8]; zg += p[16]; zo += p[24];
            }
            float iv = 1.f / (1.f + __expf(-zi));
            float fv = 1.f / (1.f + __expf(-zf));
            float gv = tanhf(zg);
            float ov = 1.f / (1.f + __expf(-zo));
            cst = fv * cst + iv * gv;
            float hvf = ov * tanhf(cst);
            hbuf[(size_t)t * BB * HH + b * HH + lx * 8 + u] = __float2half(hvf);
            if (GRP == 1)
                outp[((size_t)b * TSTEPS + (t - 1)) * HH + lx * 8 + u] = hvf;
        }
        __syncthreads();
        if (tid == 0) red_rel(own);   // release: h[t] published

#pragma unroll
        for (int i = 0; i < 16; i++) acc[i] = 0.f;

        if (GRP == 0 && t < TSTEPS) {   // x(t+1) GEMM in the publish shadow
            uint32_t ax[4][4];
            load_afrag<4>(ax, g_xh + (size_t)t * BB * 256 + kq * 64, 256, m0, lane);
            gemm_frag<4>(acc, ax, smb + W_OFF, ROWB, kq * 8, lane);
        }
    }
}

__global__ void __launch_bounds__(512, 1) lstm_fused(
        const float* __restrict__ Wih0, const float* __restrict__ Whh0,
        const float* __restrict__ bih0, const float* __restrict__ bhh0,
        const float* __restrict__ Wih1, const float* __restrict__ Whh1,
        const float* __restrict__ bih1, const float* __restrict__ bhh1,
        float* __restrict__ outp) {
    extern __shared__ char dsm[];
    int bx = blockIdx.x;
    if (bx < 64) run_group<0>(dsm, bx,      Wih0, Whh0, bih0, bhh0, nullptr);
    else         run_group<1>(dsm, bx - 64, Wih1, Whh1, bih1, bhh1, outp);
}

// smem: 1024 + 32*2048 (W, grp1 worst) + 40960 (stash) = 107520; round up
#define SMEM_SZ 108544

// ---------------- host launcher ----------------
extern "C" void kernel_launch(void* const* d_in, const int* in_sizes, int n_in,
                              void* d_out, int out_size) {
    const float* x    = (const float*)d_in[0];
    const float* Wih0 = (const float*)d_in[1];
    const float* Whh0 = (const float*)d_in[2];
    const float* bih0 = (const float*)d_in[3];
    const float* bhh0 = (const float*)d_in[4];
    const float* Wih1 = (const float*)d_in[5];
    const float* Whh1 = (const float*)d_in[6];
    const float* bih1 = (const float*)d_in[7];
    const float* bhh1 = (const float*)d_in[8];
    float* out = (float*)d_out;

    cudaFuncSetAttribute(lstm_fused, cudaFuncAttributeMaxDynamicSharedMemorySize, SMEM_SZ);

    init_k<<<16384, 256>>>(x);
    lstm_fused<<<128, 512, SMEM_SZ>>>(Wih0, Whh0, bih0, bhh0,
                                      Wih1, Whh1, bih1, bhh1, out);
}

// round 16
// speedup vs baseline: 1.7572x; 1.7572x over previous
#include <cuda_runtime.h>
#include <cuda_fp16.h>
#include <cstdint>

#define BB 64
#define TSTEPS 512
#define HH 512

// ---------------- static device scratch ----------------
__device__ __align__(16) __half g_xh[TSTEPS * BB * 256];        // x fp16, [T][B][256]
__device__ __align__(16) __half g_h0[(TSTEPS + 1) * BB * HH];   // layer0 h seq, slot0 = 0
__device__ __align__(16) __half g_h1[(TSTEPS + 1) * BB * HH];   // layer1 h seq, slot0 = 0
// quartered monotonic counters: counter q (0..3) on its own 128B line
__device__ unsigned g_q0[4 * 32];
__device__ unsigned g_q1[4 * 32];

// ---------------- PTX helpers ----------------
__device__ __forceinline__ void cp16(uint32_t dst, const void* src) {
    asm volatile("cp.async.cg.shared.global [%0], [%1], 16;\n" :: "r"(dst), "l"(src));
}
__device__ __forceinline__ void cp_commit() { asm volatile("cp.async.commit_group;\n"); }
template<int N> __device__ __forceinline__ void cp_wait() {
    asm volatile("cp.async.wait_group %0;\n" :: "n"(N));
}
__device__ __forceinline__ void ldsm4(uint32_t& r0, uint32_t& r1, uint32_t& r2, uint32_t& r3,
                                      uint32_t a) {
    asm volatile("ldmatrix.sync.aligned.m8n8.x4.shared.b16 {%0,%1,%2,%3}, [%4];\n"
                 : "=r"(r0), "=r"(r1), "=r"(r2), "=r"(r3) : "r"(a));
}
__device__ __forceinline__ void mma16816(float* c,
                                         uint32_t a0, uint32_t a1, uint32_t a2, uint32_t a3,
                                         uint32_t b0, uint32_t b1) {
    asm volatile("mma.sync.aligned.m16n8k16.row.col.f32.f16.f16.f32 "
                 "{%0,%1,%2,%3}, {%4,%5,%6,%7}, {%8,%9}, {%0,%1,%2,%3};\n"
                 : "+f"(c[0]), "+f"(c[1]), "+f"(c[2]), "+f"(c[3])
                 : "r"(a0), "r"(a1), "r"(a2), "r"(a3), "r"(b0), "r"(b1));
}
__device__ __forceinline__ unsigned ld_acq(const unsigned* p) {
    unsigned v;
    asm volatile("ld.acquire.gpu.global.u32 %0, [%1];" : "=r"(v) : "l"(p) : "memory");
    return v;
}
__device__ __forceinline__ void red_rel(unsigned* p) {
    asm volatile("red.release.gpu.global.add.u32 [%0], 1;" :: "l"(p) : "memory");
}
__device__ __forceinline__ void wpoll(const unsigned* p, unsigned v) {
    while (ld_acq(p) < v) {}
}

// ---------------- warp-private A staging: 16 rows x U units into private buffer ----------------
// src pre-offset to (warp's m-row 0, warp's k base). arb = buffer row stride bytes.
template<int U>
__device__ __forceinline__ void stage_p(uint32_t buf, int arb, const __half* src, int S,
                                        int uoff, int lane) {
#pragma unroll
    for (int i = 0; i < 16 * U / 32; i++) {
        int idx = lane + i * 32;
        int r = idx / U, u = idx % U;
        cp16(buf + r * arb + (((u + uoff) ^ (r & 7)) << 4), src + (size_t)r * S + u * 8);
    }
}

// ---------------- warp-private GEMM: 16 rows x 32 cols over NP*4 units of K ----------------
template<int NP>
__device__ __forceinline__ void gemm_p(float* acc, uint32_t abuf, int arb, int au0,
                                       uint32_t wsmb, int rowb, int wu0, int lane) {
    int rA = lane & 15;
    uint32_t abase = abuf + rA * arb;
    int asw = rA & 7, akc = lane >> 4;
    int bm = lane >> 3, bsw = lane & 7;
    uint32_t bb0 = wsmb + (lane & 7) * rowb;
#pragma unroll
    for (int p = 0; p < NP; p++) {
        int au = au0 + 4 * p, wu = wu0 + 4 * p;
        uint32_t a0, a1, a2, a3, a4, a5, a6, a7;
        ldsm4(a0, a1, a2, a3, abase + (((au + akc) ^ asw) << 4));
        ldsm4(a4, a5, a6, a7, abase + (((au + 2 + akc) ^ asw) << 4));
#pragma unroll
        for (int nt = 0; nt < 4; nt++) {
            uint32_t b0, b1, b2, b3;
            ldsm4(b0, b1, b2, b3, bb0 + nt * 8 * rowb + (((wu + bm) ^ bsw) << 4));
            mma16816(acc + nt * 4, a0, a1, a2, a3, b0, b1);
            mma16816(acc + nt * 4, a4, a5, a6, a7, b2, b3);
        }
    }
}

// ---------------- init kernel: x convert + h slot0 zero + counters ----------------
__global__ void init_k(const float* __restrict__ x) {
    int i = blockIdx.x * 256 + threadIdx.x;
    int f2 = i & 127;
    int t  = (i >> 7) & 511;
    int b  = i >> 16;
    float2 v = *(const float2*)(x + ((b * 512 + t) * 256 + f2 * 2));
    *((__half2*)(g_xh + (t * 64 + b) * 256 + f2 * 2)) = __floats2half2_rn(v.x, v.y);
    if (i < 16384) {
        __half2 z = __floats2half2_rn(0.f, 0.f);
        ((__half2*)g_h0)[i] = z;
        ((__half2*)g_h1)[i] = z;
    }
    if (i < 128) { g_q0[i] = 0; g_q1[i] = 0; }
}

// ---------------- fused two-layer pipelined persistent kernel ----------------
// CTAs [0,64): layer 0.  CTAs [64,128): layer 1, one step behind.
// 512 threads = 16 warps = 4(m) x 4(k-quarter). Warp-private A staging (no block
// sync before gemm); quartered handoff counters (16 producers per counter).
template<int GRP>
__device__ __forceinline__ void run_group(char* dsm, int lx,
        const float* __restrict__ Wih, const float* __restrict__ Whh,
        const float* __restrict__ bih, const float* __restrict__ bhh,
        float* __restrict__ outp) {
    constexpr int KIN  = GRP ? 512 : 256;
    constexpr int KTOT = KIN + 512;
    constexpr int ROWB = KTOT * 2;                       // W smem row bytes
    constexpr int W_OFF = 1024;
    constexpr int A_OFF = W_OFF + 32 * ROWB;             // warp-private A buffers
    constexpr int A_WB  = GRP ? 8192 : 4096;             // bytes per warp buffer
    constexpr int A_ARB = GRP ? 512 : 256;               // buffer row stride
    // grp0 extras: x buffers + dedicated stash; grp1: stash aliases A region
    constexpr int X_OFF = A_OFF + 16 * 4096;             // grp0 only: 16 x 2KB
    const int ST_OFF = GRP ? A_OFF : (X_OFF + 32768);

    uint32_t smb = (uint32_t)__cvta_generic_to_shared(dsm);
    float* stash = (float*)(dsm + ST_OFF);               // 4 x [64 rows x 40 floats]
    float* bsm   = (float*)(dsm + 64);

    __half* hbuf = GRP ? g_h1 : g_h0;
    unsigned* ownq = (GRP ? g_q1 : g_q0);

    int tid = threadIdx.x, lane = tid & 31, w = tid >> 5;
    int m0 = (w & 3) * 16, kq = w >> 2;
    uint32_t abuf = smb + A_OFF + w * A_WB;
    uint32_t xbuf = smb + X_OFF + w * 2048;

    // ---- load & convert W slice: 32 rows ([Wih|Whh] along k), swizzled fp16, resident ----
    for (int idx = tid; idx < 32 * (KTOT / 4); idx += 512) {
        int n  = idx / (KTOT / 4);
        int kk = (idx % (KTOT / 4)) * 4;
        int gr = (n >> 3) * HH + lx * 8 + (n & 7);
        float4 v = (kk < KIN) ? *(const float4*)(Wih + (size_t)gr * KIN + kk)
                              : *(const float4*)(Whh + (size_t)gr * HH + (kk - KIN));
        __half2 p0 = __floats2half2_rn(v.x, v.y);
        __half2 p1 = __floats2half2_rn(v.z, v.w);
        char* dst = dsm + W_OFF + n * ROWB + (((kk >> 3) ^ (n & 7)) << 4) + (kk & 7) * 2;
        *(__half2*)dst       = p0;
        *(__half2*)(dst + 4) = p1;
    }
    if (tid < 32) {
        int gr = (tid >> 3) * HH + lx * 8 + (tid & 7);
        bsm[tid] = bih[gr] + bhh[gr];
    }
    __syncthreads();

    float cst = 0.f;                                     // c-state for (b=tid>>3, u=tid&7)
    float acc[16];
#pragma unroll
    for (int i = 0; i < 16; i++) acc[i] = 0.f;

    if (GRP == 0) {   // prologue: x contribution for step 1 (warp-private)
        stage_p<8>(xbuf, 128, g_xh + (size_t)m0 * 256 + kq * 64, 256, 0, lane);
        cp_commit(); cp_wait<0>(); __syncwarp();
        gemm_p<2>(acc, xbuf, 128, 0, smb + W_OFF, ROWB, kq * 8, lane);
    }

    for (int t = 1; t <= TSTEPS; t++) {
        if (GRP == 0) {
            // own recurrence quarter: poll 16 producers, warp-private stage + gemm
            wpoll(&g_q0[kq * 32], 16u * (t - 1));
            stage_p<16>(abuf, A_ARB,
                        g_h0 + (size_t)(t - 1) * BB * HH + (size_t)m0 * HH + kq * 128,
                        512, 0, lane);
            cp_commit(); cp_wait<0>(); __syncwarp();
            gemm_p<4>(acc, abuf, A_ARB, 0, smb + W_OFF, ROWB, 32 + kq * 16, lane);
        } else {
            // h0[t] quarter (group0 ahead -> poll near-instant), then own h1[t-1]
            wpoll(&g_q0[kq * 32], 16u * t);
            stage_p<16>(abuf, A_ARB,
                        g_h0 + (size_t)t * BB * HH + (size_t)m0 * HH + kq * 128,
                        512, 0, lane);
            cp_commit();
            wpoll(&g_q1[kq * 32], 16u * (t - 1));
            stage_p<16>(abuf, A_ARB,
                        g_h1 + (size_t)(t - 1) * BB * HH + (size_t)m0 * HH + kq * 128,
                        512, 16, lane);
            cp_commit();
            cp_wait<1>(); __syncwarp();
            gemm_p<4>(acc, abuf, A_ARB, 0,  smb + W_OFF, ROWB, kq * 16, lane);       // h0
            cp_wait<0>(); __syncwarp();
            gemm_p<4>(acc, abuf, A_ARB, 16, smb + W_OFF, ROWB, 64 + kq * 16, lane);  // h1
            __syncthreads();   // stash aliases A region: all gemm reads must finish
        }

        // ---- stash partials (grp0: dedicated region, no pre-sync) ----
        {
            float* sp = stash + kq * 2560;
            int r0 = m0 + (lane >> 2), cb = 2 * (lane & 3);
#pragma unroll
            for (int nt = 0; nt < 4; nt++) {
                *(float2*)(sp + r0 * 40 + nt * 8 + cb)       =
                    make_float2(acc[nt * 4],     acc[nt * 4 + 1]);
                *(float2*)(sp + (r0 + 8) * 40 + nt * 8 + cb) =
                    make_float2(acc[nt * 4 + 2], acc[nt * 4 + 3]);
            }
        }
        __syncthreads();

        // ---- pointwise LSTM: thread owns (b = tid>>3, u = tid&7) ----
        {
            int b = tid >> 3, u = tid & 7;
            float zi = bsm[u], zf = bsm[8 + u], zg = bsm[16 + u], zo = bsm[24 + u];
#pragma unroll
            for (int q = 0; q < 4; q++) {
                const float* p = stash + q * 2560 + b * 40 + u;
                zi += p[0]; zf += p[8]; zg += p[16]; zo += p[24];
            }
            float iv = 1.f / (1.f + __expf(-zi));
            float fv = 1.f / (1.f + __expf(-zf));
            float gv = tanhf(zg);
            float ov = 1.f / (1.f + __expf(-zo));
            cst = fv * cst + iv * gv;
            float hvf = ov * tanhf(cst);
            hbuf[(size_t)t * BB * HH + b * HH + lx * 8 + u] = __float2half(hvf);
            if (GRP == 1)
                outp[((size_t)b * TSTEPS + (t - 1)) * HH + lx * 8 + u] = hvf;
        }
        __syncthreads();
        if (tid == 0) red_rel(&ownq[(lx >> 4) * 32]);    // publish to own quarter counter

#pragma unroll
        for (int i = 0; i < 16; i++) acc[i] = 0.f;

        if (GRP == 0 && t < TSTEPS) {   // x(t+1) GEMM, fully warp-private
            stage_p<8>(xbuf, 128, g_xh + (size_t)t * BB * 256 + (size_t)m0 * 256 + kq * 64,
                       256, 0, lane);
            cp_commit(); cp_wait<0>(); __syncwarp();
            gemm_p<2>(acc, xbuf, 128, 0, smb + W_OFF, ROWB, kq * 8, lane);
        }
    }
}

__global__ void __launch_bounds__(512, 1) lstm_fused(
        const float* __restrict__ Wih0, const float* __restrict__ Whh0,
        const float* __restrict__ bih0, const float* __restrict__ bhh0,
        const float* __restrict__ Wih1, const float* __restrict__ Whh1,
        const float* __restrict__ bih1, const float* __restrict__ bhh1,
        float* __restrict__ outp) {
    extern __shared__ char dsm[];
    int bx = blockIdx.x;
    if (bx < 64) run_group<0>(dsm, bx,      Wih0, Whh0, bih0, bhh0, nullptr);
    else         run_group<1>(dsm, bx - 64, Wih1, Whh1, bih1, bhh1, outp);
}

// grp1: 1024 + 65536 (W) + 131072 (A, stash aliased) = 197632
// grp0: 1024 + 49152 + 65536 + 32768 + 40960 = 189440
#define SMEM_SZ 197632

// ---------------- host launcher ----------------
extern "C" void kernel_launch(void* const* d_in, const int* in_sizes, int n_in,
                              void* d_out, int out_size) {
    const float* x    = (const float*)d_in[0];
    const float* Wih0 = (const float*)d_in[1];
    const float* Whh0 = (const float*)d_in[2];
    const float* bih0 = (const float*)d_in[3];
    const float* bhh0 = (const float*)d_in[4];
    const float* Wih1 = (const float*)d_in[5];
    const float* Whh1 = (const float*)d_in[6];
    const float* bih1 = (const float*)d_in[7];
    const float* bhh1 = (const float*)d_in[8];
    float* out = (float*)d_out;

    cudaFuncSetAttribute(lstm_fused, cudaFuncAttributeMaxDynamicSharedMemorySize, SMEM_SZ);

    init_k<<<16384, 256>>>(x);
    lstm_fused<<<128, 512, SMEM_SZ>>>(Wih0, Whh0, bih0, bhh0,
                                      Wih1, Whh1, bih1, bhh1, out);
}